// round 1
// baseline (speedup 1.0000x reference)
#include <cuda_runtime.h>
#include <math.h>
#include <stdint.h>

#define B_  2
#define L_  2048
#define D_  2048
#define HD_ 64
#define NH_ 32
#define DC_ 2048
#define EPS 1.1920929e-7f

// ---------------- scratch (device globals; no allocation) ----------------
__device__ float g_ss [B_ * 2 * D_];                 // [b][4096] shift|scale
__device__ float g_h  [(size_t)B_ * L_ * D_];        // modulated hidden
__device__ float g_qkv[(size_t)B_ * L_ * 3 * D_];    // fused qkv rows=(b,l)
__device__ float g_q  [(size_t)B_ * NH_ * L_ * HD_]; // [b][h][l][d]
__device__ float g_k  [(size_t)B_ * NH_ * L_ * HD_];
__device__ float g_v  [(size_t)B_ * NH_ * L_ * HD_];
__device__ float g_o  [(size_t)B_ * L_ * D_];        // rows=(b,l), cols=(h,d)

// ---------------- 1) ss = condition @ w_ada^T  (warp per output) ---------
__global__ void ada_kernel(const float* __restrict__ cond,
                           const float* __restrict__ w_ada) {
    int w    = (blockIdx.x * blockDim.x + threadIdx.x) >> 5;   // 0..8191
    int lane = threadIdx.x & 31;
    int b = w >> 12;
    int j = w & 4095;
    const float4* c4 = reinterpret_cast<const float4*>(cond + (size_t)b * DC_);
    const float4* w4 = reinterpret_cast<const float4*>(w_ada + (size_t)j * DC_);
    float s = 0.f;
#pragma unroll
    for (int q = 0; q < 16; q++) {
        float4 a  = c4[lane + q * 32];
        float4 bb = w4[lane + q * 32];
        s += a.x * bb.x + a.y * bb.y + a.z * bb.z + a.w * bb.w;
    }
#pragma unroll
    for (int o = 16; o; o >>= 1) s += __shfl_xor_sync(0xffffffffu, s, o);
    if (lane == 0) g_ss[b * 4096 + j] = s;
}

// ---------------- 2) h = rmsnorm(x)*(1+scale)+shift ----------------------
__global__ void rmsada_kernel(const float* __restrict__ x) {
    int row = blockIdx.x;            // 0..4095 = b*L + l
    int b   = row >> 11;
    int t   = threadIdx.x;           // 256
    const float4* xr = reinterpret_cast<const float4*>(x + (size_t)row * D_);
    float4 v0 = xr[t], v1 = xr[t + 256];
    float s = v0.x*v0.x + v0.y*v0.y + v0.z*v0.z + v0.w*v0.w
            + v1.x*v1.x + v1.y*v1.y + v1.z*v1.z + v1.w*v1.w;
    __shared__ float red[256];
    red[t] = s; __syncthreads();
    for (int o = 128; o; o >>= 1) { if (t < o) red[t] += red[t + o]; __syncthreads(); }
    float inv = rsqrtf(red[0] * (1.0f / D_) + EPS);
    const float* shift = g_ss + b * 4096;
    const float* scale = shift + D_;
    float4* hr = reinterpret_cast<float4*>(g_h + (size_t)row * D_);
    {
        int d = t * 4;
        float4 sc = *reinterpret_cast<const float4*>(scale + d);
        float4 sh = *reinterpret_cast<const float4*>(shift + d);
        float4 r;
        r.x = v0.x * inv * (1.f + sc.x) + sh.x;
        r.y = v0.y * inv * (1.f + sc.y) + sh.y;
        r.z = v0.z * inv * (1.f + sc.z) + sh.z;
        r.w = v0.w * inv * (1.f + sc.w) + sh.w;
        hr[t] = r;
    }
    {
        int d = (t + 256) * 4;
        float4 sc = *reinterpret_cast<const float4*>(scale + d);
        float4 sh = *reinterpret_cast<const float4*>(shift + d);
        float4 r;
        r.x = v1.x * inv * (1.f + sc.x) + sh.x;
        r.y = v1.y * inv * (1.f + sc.y) + sh.y;
        r.z = v1.z * inv * (1.f + sc.z) + sh.z;
        r.w = v1.w * inv * (1.f + sc.w) + sh.w;
        hr[t + 256] = r;
    }
}

// ---------------- 3/6) SGEMM NT: C[M,N] = A[M,K] * B[N,K]^T --------------
// BM=BN=128, BK=16, 256 threads, 8x8 microtile.
__global__ void gemm_nt(float* __restrict__ C, const float* __restrict__ A,
                        const float* __restrict__ B, int M, int N, int K) {
    __shared__ float As[16][128];
    __shared__ float Bs[16][128];
    int tid = threadIdx.x;
    int m0 = blockIdx.y * 128;
    int n0 = blockIdx.x * 128;
    int ty = tid >> 4, tx = tid & 15;
    float acc[8][8] = {};
    for (int k0 = 0; k0 < K; k0 += 16) {
#pragma unroll
        for (int t = 0; t < 2; t++) {
            int f  = tid + t * 256;        // 0..511
            int m  = f >> 2;               // 0..127
            int kq = (f & 3) * 4;          // 0,4,8,12
            float4 va = *reinterpret_cast<const float4*>(A + (size_t)(m0 + m) * K + k0 + kq);
            As[kq + 0][m] = va.x; As[kq + 1][m] = va.y;
            As[kq + 2][m] = va.z; As[kq + 3][m] = va.w;
            float4 vb = *reinterpret_cast<const float4*>(B + (size_t)(n0 + m) * K + k0 + kq);
            Bs[kq + 0][m] = vb.x; Bs[kq + 1][m] = vb.y;
            Bs[kq + 2][m] = vb.z; Bs[kq + 3][m] = vb.w;
        }
        __syncthreads();
#pragma unroll
        for (int k = 0; k < 16; k++) {
            float4 a0 = *reinterpret_cast<const float4*>(&As[k][ty * 8]);
            float4 a1 = *reinterpret_cast<const float4*>(&As[k][ty * 8 + 4]);
            float4 b0 = *reinterpret_cast<const float4*>(&Bs[k][tx * 8]);
            float4 b1 = *reinterpret_cast<const float4*>(&Bs[k][tx * 8 + 4]);
            float a[8] = {a0.x, a0.y, a0.z, a0.w, a1.x, a1.y, a1.z, a1.w};
            float b[8] = {b0.x, b0.y, b0.z, b0.w, b1.x, b1.y, b1.z, b1.w};
#pragma unroll
            for (int i = 0; i < 8; i++)
#pragma unroll
                for (int j = 0; j < 8; j++)
                    acc[i][j] += a[i] * b[j];
        }
        __syncthreads();
    }
#pragma unroll
    for (int i = 0; i < 8; i++)
#pragma unroll
        for (int j = 0; j < 8; j += 4) {
            float4 v = make_float4(acc[i][j], acc[i][j+1], acc[i][j+2], acc[i][j+3]);
            *reinterpret_cast<float4*>(C + (size_t)(m0 + ty * 8 + i) * N + n0 + tx * 8 + j) = v;
        }
}

// ---------------- 4) per-head rmsnorm + qk_w + RoPE, split q/k/v ---------
__global__ void qkrope_kernel(const float* __restrict__ rope,
                              const float* __restrict__ qkw) {
    int wid  = (blockIdx.x * blockDim.x + threadIdx.x) >> 5;  // 0..131071 = (b*32+h)*2048+l
    int lane = threadIdx.x & 31;
    int b   = wid >> 16;
    int rem = wid & 65535;
    int h   = rem >> 11;
    int l   = rem & 2047;
    size_t rowoff = (size_t)(b * L_ + l) * (3 * D_);
    int col = h * HD_ + lane * 2;
    float2 q = *reinterpret_cast<const float2*>(g_qkv + rowoff + col);
    float2 k = *reinterpret_cast<const float2*>(g_qkv + rowoff + D_ + col);
    float2 v = *reinterpret_cast<const float2*>(g_qkv + rowoff + 2 * D_ + col);
    float sq = q.x * q.x + q.y * q.y;
    float sk = k.x * k.x + k.y * k.y;
#pragma unroll
    for (int o = 16; o; o >>= 1) {
        sq += __shfl_xor_sync(0xffffffffu, sq, o);
        sk += __shfl_xor_sync(0xffffffffu, sk, o);
    }
    float qi = rsqrtf(sq * (1.0f / HD_) + EPS);
    float ki = rsqrtf(sk * (1.0f / HD_) + EPS);
    float2 w2 = *reinterpret_cast<const float2*>(qkw + lane * 2);
    float q0 = q.x * qi * w2.x, q1 = q.y * qi * w2.y;
    float k0 = k.x * ki * w2.x, k1 = k.y * ki * w2.y;
    float2 r0 = *reinterpret_cast<const float2*>(rope + (size_t)l * HD_ + lane * 2);
    float2 r1 = *reinterpret_cast<const float2*>(rope + (size_t)(L_ + l) * HD_ + lane * 2);
    // x_hat[2i] = -x[2i+1], x_hat[2i+1] = x[2i]
    float2 qo, ko;
    qo.x = q0 * r0.x - q1 * r1.x;
    qo.y = q1 * r0.y + q0 * r1.y;
    ko.x = k0 * r0.x - k1 * r1.x;
    ko.y = k1 * r0.y + k0 * r1.y;
    size_t orow = (size_t)wid * HD_ + lane * 2;
    *reinterpret_cast<float2*>(g_q + orow) = qo;
    *reinterpret_cast<float2*>(g_k + orow) = ko;
    *reinterpret_cast<float2*>(g_v + orow) = v;
}

// ---------------- 5) flash attention: BQ=64, BC=32, static smem <48KB ----
__global__ void attn_kernel() {
    __shared__ float Qs[64 * 65];   // q tile (pre-scaled by 1/8), stride 65
    __shared__ float Ks[32 * 65];   // k chunk, stride 65
    __shared__ float Vs[32 * 64];   // v chunk, stride 64
    __shared__ float Ss[64 * 33];   // scores / probs, stride 33
    __shared__ float mrow[64], lrow[64], crow[64];

    int tid = threadIdx.x;           // 256
    int bh  = blockIdx.y;            // b*32+h
    int bq0 = blockIdx.x * 64;
    const float* Qg = g_q + (size_t)bh * L_ * HD_;
    const float* Kg = g_k + (size_t)bh * L_ * HD_;
    const float* Vg = g_v + (size_t)bh * L_ * HD_;

    // load Q tile, scaled by softmax scale 1/sqrt(64)
#pragma unroll
    for (int f = tid; f < 1024; f += 256) {
        int r = f >> 4, c = (f & 15) * 4;
        float4 v = *reinterpret_cast<const float4*>(Qg + (size_t)(bq0 + r) * HD_ + c);
        Qs[r * 65 + c + 0] = v.x * 0.125f;
        Qs[r * 65 + c + 1] = v.y * 0.125f;
        Qs[r * 65 + c + 2] = v.z * 0.125f;
        Qs[r * 65 + c + 3] = v.w * 0.125f;
    }
    if (tid < 64) { mrow[tid] = -INFINITY; lrow[tid] = 0.f; }

    float acc[4][4] = {};            // rows (tid>>4)*4+i, cols (tid&15)*4+j
    __syncthreads();

    for (int kc = 0; kc < L_; kc += 32) {
        // load K,V chunk (32 rows)
#pragma unroll
        for (int f = tid; f < 512; f += 256) {
            int r = f >> 4, c = (f & 15) * 4;
            float4 kv = *reinterpret_cast<const float4*>(Kg + (size_t)(kc + r) * HD_ + c);
            Ks[r * 65 + c + 0] = kv.x; Ks[r * 65 + c + 1] = kv.y;
            Ks[r * 65 + c + 2] = kv.z; Ks[r * 65 + c + 3] = kv.w;
            float4 vv = *reinterpret_cast<const float4*>(Vg + (size_t)(kc + r) * HD_ + c);
            *reinterpret_cast<float4*>(&Vs[r * 64 + c]) = vv;
        }
        __syncthreads();

        // S[64][32] = Qs * Ks^T  (thread tile 2 rows x 4 cols)
        {
            int ry = tid >> 3;       // 0..31 -> rows ry*2..+1
            int cx = tid & 7;        // 0..7  -> cols cx*4..+3
            float s[2][4] = {};
#pragma unroll 8
            for (int d = 0; d < 64; d++) {
                float a0 = Qs[(ry * 2 + 0) * 65 + d];
                float a1 = Qs[(ry * 2 + 1) * 65 + d];
                float b0 = Ks[(cx * 4 + 0) * 65 + d];
                float b1 = Ks[(cx * 4 + 1) * 65 + d];
                float b2 = Ks[(cx * 4 + 2) * 65 + d];
                float b3 = Ks[(cx * 4 + 3) * 65 + d];
                s[0][0] += a0 * b0; s[0][1] += a0 * b1; s[0][2] += a0 * b2; s[0][3] += a0 * b3;
                s[1][0] += a1 * b0; s[1][1] += a1 * b1; s[1][2] += a1 * b2; s[1][3] += a1 * b3;
            }
#pragma unroll
            for (int i = 0; i < 2; i++)
#pragma unroll
                for (int j = 0; j < 4; j++)
                    Ss[(ry * 2 + i) * 33 + cx * 4 + j] = s[i][j];
        }
        __syncthreads();

        // online softmax (4 threads per row, 8 cols each)
        {
            int r = tid >> 2, p = tid & 3;
            float* srow = Ss + r * 33 + p * 8;
            float mx = -INFINITY;
#pragma unroll
            for (int c = 0; c < 8; c++) mx = fmaxf(mx, srow[c]);
            mx = fmaxf(mx, __shfl_xor_sync(0xffffffffu, mx, 1));
            mx = fmaxf(mx, __shfl_xor_sync(0xffffffffu, mx, 2));
            float mold = mrow[r];
            float mnew = fmaxf(mold, mx);
            float sum = 0.f;
#pragma unroll
            for (int c = 0; c < 8; c++) {
                float e = __expf(srow[c] - mnew);
                srow[c] = e;
                sum += e;
            }
            sum += __shfl_xor_sync(0xffffffffu, sum, 1);
            sum += __shfl_xor_sync(0xffffffffu, sum, 2);
            if (p == 0) {
                float cf = __expf(mold - mnew);
                mrow[r] = mnew;
                lrow[r] = lrow[r] * cf + sum;
                crow[r] = cf;
            }
        }
        __syncthreads();

        // O = O*corr + P @ V   (thread tile 4x4, rows (tid>>4)*4+i)
        {
            int ty = tid >> 4, tx = tid & 15;
            float cf[4];
#pragma unroll
            for (int i = 0; i < 4; i++) cf[i] = crow[ty * 4 + i];
#pragma unroll
            for (int i = 0; i < 4; i++)
#pragma unroll
                for (int j = 0; j < 4; j++) acc[i][j] *= cf[i];
#pragma unroll 8
            for (int kk = 0; kk < 32; kk++) {
                float p0 = Ss[(ty * 4 + 0) * 33 + kk];
                float p1 = Ss[(ty * 4 + 1) * 33 + kk];
                float p2 = Ss[(ty * 4 + 2) * 33 + kk];
                float p3 = Ss[(ty * 4 + 3) * 33 + kk];
                float v0 = Vs[kk * 64 + tx * 4 + 0];
                float v1 = Vs[kk * 64 + tx * 4 + 1];
                float v2 = Vs[kk * 64 + tx * 4 + 2];
                float v3 = Vs[kk * 64 + tx * 4 + 3];
                acc[0][0] += p0 * v0; acc[0][1] += p0 * v1; acc[0][2] += p0 * v2; acc[0][3] += p0 * v3;
                acc[1][0] += p1 * v0; acc[1][1] += p1 * v1; acc[1][2] += p1 * v2; acc[1][3] += p1 * v3;
                acc[2][0] += p2 * v0; acc[2][1] += p2 * v1; acc[2][2] += p2 * v2; acc[2][3] += p2 * v3;
                acc[3][0] += p3 * v0; acc[3][1] += p3 * v1; acc[3][2] += p3 * v2; acc[3][3] += p3 * v3;
            }
        }
        __syncthreads();
    }

    // epilogue: divide by l, write to g_o[(b,l_q), (h,d)]
    int b = bh >> 5, h = bh & 31;
    int ty = tid >> 4, tx = tid & 15;
#pragma unroll
    for (int i = 0; i < 4; i++) {
        int r = ty * 4 + i;
        float inv = 1.f / lrow[r];
        float* dst = g_o + (size_t)(b * L_ + bq0 + r) * D_ + h * HD_ + tx * 4;
        float4 v = make_float4(acc[i][0] * inv, acc[i][1] * inv,
                               acc[i][2] * inv, acc[i][3] * inv);
        *reinterpret_cast<float4*>(dst) = v;
    }
}

// -------------------------------------------------------------------------
extern "C" void kernel_launch(void* const* d_in, const int* in_sizes, int n_in,
                              void* d_out, int out_size) {
    const float* x     = (const float*)d_in[0];
    const float* cond  = (const float*)d_in[1];
    const float* rope  = (const float*)d_in[2];
    const float* w_ada = (const float*)d_in[3];
    const float* w_qkv = (const float*)d_in[4];
    const float* w_out = (const float*)d_in[5];
    const float* qk_w  = (const float*)d_in[6];
    float* out = (float*)d_out;

    void* p;
    cudaGetSymbolAddress(&p, g_h);   float* ph   = (float*)p;
    cudaGetSymbolAddress(&p, g_qkv); float* pqkv = (float*)p;
    cudaGetSymbolAddress(&p, g_o);   float* po   = (float*)p;

    ada_kernel<<<1024, 256>>>(cond, w_ada);
    rmsada_kernel<<<B_ * L_, 256>>>(x);
    gemm_nt<<<dim3(3 * D_ / 128, B_ * L_ / 128), 256>>>(pqkv, ph, w_qkv,
                                                        B_ * L_, 3 * D_, D_);
    qkrope_kernel<<<(B_ * NH_ * L_) / 8, 256>>>(rope, qk_w);
    attn_kernel<<<dim3(L_ / 64, B_ * NH_), 256>>>();
    gemm_nt<<<dim3(D_ / 128, B_ * L_ / 128), 256>>>(out, po, w_out,
                                                    B_ * L_, D_, D_);
}

// round 3
// speedup vs baseline: 1.6785x; 1.6785x over previous
#include <cuda_runtime.h>
#include <math.h>
#include <stdint.h>

#define B_  2
#define L_  2048
#define D_  2048
#define HD_ 64
#define NH_ 32
#define DC_ 2048
#define EPS 1.1920929e-7f

// ---------------- scratch (device globals; no allocation) ----------------
__device__ float g_ss [B_ * 2 * D_];                 // [b][4096] shift|scale
__device__ float g_h  [(size_t)B_ * L_ * D_];        // modulated hidden
__device__ float g_qkv[(size_t)B_ * L_ * 3 * D_];    // fused qkv rows=(b,l)
__device__ float g_q  [(size_t)B_ * NH_ * L_ * HD_]; // [b][h][l][d]
__device__ float g_k  [(size_t)B_ * NH_ * L_ * HD_];
__device__ float g_v  [(size_t)B_ * NH_ * L_ * HD_];
__device__ float g_o  [(size_t)B_ * L_ * D_];        // rows=(b,l), cols=(h,d)

// ---------------- tf32 helpers ------------------------------------------
__device__ __forceinline__ uint32_t f2tf32(float x) {
    uint32_t u;
    asm("cvt.rna.tf32.f32 %0, %1;" : "=r"(u) : "f"(x));
    return u;
}

__device__ __forceinline__ void mma_tf32(float* c, const uint32_t* a,
                                         const uint32_t* b) {
    asm volatile(
        "mma.sync.aligned.m16n8k8.row.col.f32.tf32.tf32.f32 "
        "{%0,%1,%2,%3}, {%4,%5,%6,%7}, {%8,%9}, {%0,%1,%2,%3};"
        : "+f"(c[0]), "+f"(c[1]), "+f"(c[2]), "+f"(c[3])
        : "r"(a[0]), "r"(a[1]), "r"(a[2]), "r"(a[3]), "r"(b[0]), "r"(b[1]));
}

// ============ tensor-core GEMM NT: C[M,N] = A[M,K] * B[N,K]^T ============
// BM=BN=128, BK=16, 256 threads (8 warps, 2x4), warp tile 64x32.
// smem [row][20] padding => conflict-free tf32 fragment loads.
__global__ void __launch_bounds__(256, 2)
gemm_mma(float* __restrict__ C, const float* __restrict__ A,
         const float* __restrict__ B, int M, int N, int K) {
    __shared__ uint32_t As[2][128][20];
    __shared__ uint32_t Bs[2][128][20];

    int tid  = threadIdx.x;
    int m0   = blockIdx.y * 128, n0 = blockIdx.x * 128;
    int wid  = tid >> 5, lane = tid & 31;
    int wm   = (wid & 1) * 64;       // warp m-offset
    int wn   = (wid >> 1) * 32;      // warp n-offset
    int qr   = lane >> 2;            // 0..7
    int qc   = lane & 3;             // 0..3

    int lr = tid >> 2;               // 0..63 (load row, +64 second half)
    int lc = (tid & 3) * 4;          // 0,4,8,12

    const float* Ap0 = A + (size_t)(m0 + lr) * K + lc;
    const float* Ap1 = A + (size_t)(m0 + lr + 64) * K + lc;
    const float* Bp0 = B + (size_t)(n0 + lr) * K + lc;
    const float* Bp1 = B + (size_t)(n0 + lr + 64) * K + lc;

    float4 pa0 = *reinterpret_cast<const float4*>(Ap0);
    float4 pa1 = *reinterpret_cast<const float4*>(Ap1);
    float4 pb0 = *reinterpret_cast<const float4*>(Bp0);
    float4 pb1 = *reinterpret_cast<const float4*>(Bp1);

#define STORE_TILE(st)                                                        \
    do {                                                                      \
        uint4 ua0 = make_uint4(f2tf32(pa0.x), f2tf32(pa0.y),                  \
                               f2tf32(pa0.z), f2tf32(pa0.w));                 \
        uint4 ua1 = make_uint4(f2tf32(pa1.x), f2tf32(pa1.y),                  \
                               f2tf32(pa1.z), f2tf32(pa1.w));                 \
        uint4 ub0 = make_uint4(f2tf32(pb0.x), f2tf32(pb0.y),                  \
                               f2tf32(pb0.z), f2tf32(pb0.w));                 \
        uint4 ub1 = make_uint4(f2tf32(pb1.x), f2tf32(pb1.y),                  \
                               f2tf32(pb1.z), f2tf32(pb1.w));                 \
        *reinterpret_cast<uint4*>(&As[st][lr][lc])      = ua0;                \
        *reinterpret_cast<uint4*>(&As[st][lr + 64][lc]) = ua1;                \
        *reinterpret_cast<uint4*>(&Bs[st][lr][lc])      = ub0;                \
        *reinterpret_cast<uint4*>(&Bs[st][lr + 64][lc]) = ub1;                \
    } while (0)

    STORE_TILE(0);
    __syncthreads();

    float acc[4][4][4] = {};
    int s = 0;
    for (int k0 = 16; k0 <= K; k0 += 16) {
        bool last = (k0 == K);
        if (!last) {
            pa0 = *reinterpret_cast<const float4*>(Ap0 + k0);
            pa1 = *reinterpret_cast<const float4*>(Ap1 + k0);
            pb0 = *reinterpret_cast<const float4*>(Bp0 + k0);
            pb1 = *reinterpret_cast<const float4*>(Bp1 + k0);
        }
#pragma unroll
        for (int k8 = 0; k8 < 16; k8 += 8) {
            uint32_t af[4][4], bf[4][2];
#pragma unroll
            for (int mt = 0; mt < 4; mt++) {
                int m = wm + mt * 16 + qr;
                af[mt][0] = As[s][m][k8 + qc];
                af[mt][1] = As[s][m + 8][k8 + qc];
                af[mt][2] = As[s][m][k8 + qc + 4];
                af[mt][3] = As[s][m + 8][k8 + qc + 4];
            }
#pragma unroll
            for (int nt = 0; nt < 4; nt++) {
                int n = wn + nt * 8 + qr;
                bf[nt][0] = Bs[s][n][k8 + qc];
                bf[nt][1] = Bs[s][n][k8 + qc + 4];
            }
#pragma unroll
            for (int mt = 0; mt < 4; mt++)
#pragma unroll
                for (int nt = 0; nt < 4; nt++)
                    mma_tf32(acc[mt][nt], af[mt], bf[nt]);
        }
        if (!last) {
            STORE_TILE(s ^ 1);
            __syncthreads();
            s ^= 1;
        }
    }

    // epilogue: c0,c1 at (row, col..col+1), c2,c3 at (row+8, ...)
#pragma unroll
    for (int mt = 0; mt < 4; mt++) {
        int row = m0 + wm + mt * 16 + qr;
#pragma unroll
        for (int nt = 0; nt < 4; nt++) {
            int col = n0 + wn + nt * 8 + qc * 2;
            *reinterpret_cast<float2*>(C + (size_t)row * N + col) =
                make_float2(acc[mt][nt][0], acc[mt][nt][1]);
            *reinterpret_cast<float2*>(C + (size_t)(row + 8) * N + col) =
                make_float2(acc[mt][nt][2], acc[mt][nt][3]);
        }
    }
#undef STORE_TILE
}

// ---------------- 1) ss = condition @ w_ada^T  (warp per output) ---------
__global__ void ada_kernel(const float* __restrict__ cond,
                           const float* __restrict__ w_ada) {
    int w    = (blockIdx.x * blockDim.x + threadIdx.x) >> 5;   // 0..8191
    int lane = threadIdx.x & 31;
    int b = w >> 12;
    int j = w & 4095;
    const float4* c4 = reinterpret_cast<const float4*>(cond + (size_t)b * DC_);
    const float4* w4 = reinterpret_cast<const float4*>(w_ada + (size_t)j * DC_);
    float s = 0.f;
#pragma unroll
    for (int q = 0; q < 16; q++) {
        float4 a  = c4[lane + q * 32];
        float4 bb = w4[lane + q * 32];
        s += a.x * bb.x + a.y * bb.y + a.z * bb.z + a.w * bb.w;
    }
#pragma unroll
    for (int o = 16; o; o >>= 1) s += __shfl_xor_sync(0xffffffffu, s, o);
    if (lane == 0) g_ss[b * 4096 + j] = s;
}

// ---------------- 2) h = rmsnorm(x)*(1+scale)+shift ----------------------
__global__ void rmsada_kernel(const float* __restrict__ x) {
    int row = blockIdx.x;            // 0..4095 = b*L + l
    int b   = row >> 11;
    int t   = threadIdx.x;           // 256
    const float4* xr = reinterpret_cast<const float4*>(x + (size_t)row * D_);
    float4 v0 = xr[t], v1 = xr[t + 256];
    float s = v0.x*v0.x + v0.y*v0.y + v0.z*v0.z + v0.w*v0.w
            + v1.x*v1.x + v1.y*v1.y + v1.z*v1.z + v1.w*v1.w;
    __shared__ float red[256];
    red[t] = s; __syncthreads();
    for (int o = 128; o; o >>= 1) { if (t < o) red[t] += red[t + o]; __syncthreads(); }
    float inv = rsqrtf(red[0] * (1.0f / D_) + EPS);
    const float* shift = g_ss + b * 4096;
    const float* scale = shift + D_;
    float4* hr = reinterpret_cast<float4*>(g_h + (size_t)row * D_);
    {
        int d = t * 4;
        float4 sc = *reinterpret_cast<const float4*>(scale + d);
        float4 sh = *reinterpret_cast<const float4*>(shift + d);
        float4 r;
        r.x = v0.x * inv * (1.f + sc.x) + sh.x;
        r.y = v0.y * inv * (1.f + sc.y) + sh.y;
        r.z = v0.z * inv * (1.f + sc.z) + sh.z;
        r.w = v0.w * inv * (1.f + sc.w) + sh.w;
        hr[t] = r;
    }
    {
        int d = (t + 256) * 4;
        float4 sc = *reinterpret_cast<const float4*>(scale + d);
        float4 sh = *reinterpret_cast<const float4*>(shift + d);
        float4 r;
        r.x = v1.x * inv * (1.f + sc.x) + sh.x;
        r.y = v1.y * inv * (1.f + sc.y) + sh.y;
        r.z = v1.z * inv * (1.f + sc.z) + sh.z;
        r.w = v1.w * inv * (1.f + sc.w) + sh.w;
        hr[t + 256] = r;
    }
}

// ---------------- 4) per-head rmsnorm + qk_w + RoPE, split q/k/v ---------
__global__ void qkrope_kernel(const float* __restrict__ rope,
                              const float* __restrict__ qkw) {
    int wid  = (blockIdx.x * blockDim.x + threadIdx.x) >> 5;  // (b*32+h)*2048+l
    int lane = threadIdx.x & 31;
    int b   = wid >> 16;
    int rem = wid & 65535;
    int h   = rem >> 11;
    int l   = rem & 2047;
    size_t rowoff = (size_t)(b * L_ + l) * (3 * D_);
    int col = h * HD_ + lane * 2;
    float2 q = *reinterpret_cast<const float2*>(g_qkv + rowoff + col);
    float2 k = *reinterpret_cast<const float2*>(g_qkv + rowoff + D_ + col);
    float2 v = *reinterpret_cast<const float2*>(g_qkv + rowoff + 2 * D_ + col);
    float sq = q.x * q.x + q.y * q.y;
    float sk = k.x * k.x + k.y * k.y;
#pragma unroll
    for (int o = 16; o; o >>= 1) {
        sq += __shfl_xor_sync(0xffffffffu, sq, o);
        sk += __shfl_xor_sync(0xffffffffu, sk, o);
    }
    float qi = rsqrtf(sq * (1.0f / HD_) + EPS);
    float ki = rsqrtf(sk * (1.0f / HD_) + EPS);
    float2 w2 = *reinterpret_cast<const float2*>(qkw + lane * 2);
    float q0 = q.x * qi * w2.x, q1 = q.y * qi * w2.y;
    float k0 = k.x * ki * w2.x, k1 = k.y * ki * w2.y;
    float2 r0 = *reinterpret_cast<const float2*>(rope + (size_t)l * HD_ + lane * 2);
    float2 r1 = *reinterpret_cast<const float2*>(rope + (size_t)(L_ + l) * HD_ + lane * 2);
    float2 qo, ko;
    qo.x = q0 * r0.x - q1 * r1.x;
    qo.y = q1 * r0.y + q0 * r1.y;
    ko.x = k0 * r0.x - k1 * r1.x;
    ko.y = k1 * r0.y + k0 * r1.y;
    size_t orow = (size_t)wid * HD_ + lane * 2;
    *reinterpret_cast<float2*>(g_q + orow) = qo;
    *reinterpret_cast<float2*>(g_k + orow) = ko;
    *reinterpret_cast<float2*>(g_v + orow) = v;
}

// ---------------- 5) flash attention: BQ=64, BC=32, static smem <48KB ----
__global__ void attn_kernel() {
    __shared__ float Qs[64 * 65];
    __shared__ float Ks[32 * 65];
    __shared__ float Vs[32 * 64];
    __shared__ float Ss[64 * 33];
    __shared__ float mrow[64], lrow[64], crow[64];

    int tid = threadIdx.x;           // 256
    int bh  = blockIdx.y;            // b*32+h
    int bq0 = blockIdx.x * 64;
    const float* Qg = g_q + (size_t)bh * L_ * HD_;
    const float* Kg = g_k + (size_t)bh * L_ * HD_;
    const float* Vg = g_v + (size_t)bh * L_ * HD_;

#pragma unroll
    for (int f = tid; f < 1024; f += 256) {
        int r = f >> 4, c = (f & 15) * 4;
        float4 v = *reinterpret_cast<const float4*>(Qg + (size_t)(bq0 + r) * HD_ + c);
        Qs[r * 65 + c + 0] = v.x * 0.125f;
        Qs[r * 65 + c + 1] = v.y * 0.125f;
        Qs[r * 65 + c + 2] = v.z * 0.125f;
        Qs[r * 65 + c + 3] = v.w * 0.125f;
    }
    if (tid < 64) { mrow[tid] = -INFINITY; lrow[tid] = 0.f; }

    float acc[4][4] = {};
    __syncthreads();

    for (int kc = 0; kc < L_; kc += 32) {
#pragma unroll
        for (int f = tid; f < 512; f += 256) {
            int r = f >> 4, c = (f & 15) * 4;
            float4 kv = *reinterpret_cast<const float4*>(Kg + (size_t)(kc + r) * HD_ + c);
            Ks[r * 65 + c + 0] = kv.x; Ks[r * 65 + c + 1] = kv.y;
            Ks[r * 65 + c + 2] = kv.z; Ks[r * 65 + c + 3] = kv.w;
            float4 vv = *reinterpret_cast<const float4*>(Vg + (size_t)(kc + r) * HD_ + c);
            *reinterpret_cast<float4*>(&Vs[r * 64 + c]) = vv;
        }
        __syncthreads();

        {
            int ry = tid >> 3;
            int cx = tid & 7;
            float s[2][4] = {};
#pragma unroll 8
            for (int d = 0; d < 64; d++) {
                float a0 = Qs[(ry * 2 + 0) * 65 + d];
                float a1 = Qs[(ry * 2 + 1) * 65 + d];
                float b0 = Ks[(cx * 4 + 0) * 65 + d];
                float b1 = Ks[(cx * 4 + 1) * 65 + d];
                float b2 = Ks[(cx * 4 + 2) * 65 + d];
                float b3 = Ks[(cx * 4 + 3) * 65 + d];
                s[0][0] += a0 * b0; s[0][1] += a0 * b1; s[0][2] += a0 * b2; s[0][3] += a0 * b3;
                s[1][0] += a1 * b0; s[1][1] += a1 * b1; s[1][2] += a1 * b2; s[1][3] += a1 * b3;
            }
#pragma unroll
            for (int i = 0; i < 2; i++)
#pragma unroll
                for (int j = 0; j < 4; j++)
                    Ss[(ry * 2 + i) * 33 + cx * 4 + j] = s[i][j];
        }
        __syncthreads();

        {
            int r = tid >> 2, p = tid & 3;
            float* srow = Ss + r * 33 + p * 8;
            float mx = -INFINITY;
#pragma unroll
            for (int c = 0; c < 8; c++) mx = fmaxf(mx, srow[c]);
            mx = fmaxf(mx, __shfl_xor_sync(0xffffffffu, mx, 1));
            mx = fmaxf(mx, __shfl_xor_sync(0xffffffffu, mx, 2));
            float mold = mrow[r];
            float mnew = fmaxf(mold, mx);
            float sum = 0.f;
#pragma unroll
            for (int c = 0; c < 8; c++) {
                float e = __expf(srow[c] - mnew);
                srow[c] = e;
                sum += e;
            }
            sum += __shfl_xor_sync(0xffffffffu, sum, 1);
            sum += __shfl_xor_sync(0xffffffffu, sum, 2);
            if (p == 0) {
                float cf = __expf(mold - mnew);
                mrow[r] = mnew;
                lrow[r] = lrow[r] * cf + sum;
                crow[r] = cf;
            }
        }
        __syncthreads();

        {
            int ty = tid >> 4, tx = tid & 15;
            float cf[4];
#pragma unroll
            for (int i = 0; i < 4; i++) cf[i] = crow[ty * 4 + i];
#pragma unroll
            for (int i = 0; i < 4; i++)
#pragma unroll
                for (int j = 0; j < 4; j++) acc[i][j] *= cf[i];
#pragma unroll 8
            for (int kk = 0; kk < 32; kk++) {
                float p0 = Ss[(ty * 4 + 0) * 33 + kk];
                float p1 = Ss[(ty * 4 + 1) * 33 + kk];
                float p2 = Ss[(ty * 4 + 2) * 33 + kk];
                float p3 = Ss[(ty * 4 + 3) * 33 + kk];
                float v0 = Vs[kk * 64 + tx * 4 + 0];
                float v1 = Vs[kk * 64 + tx * 4 + 1];
                float v2 = Vs[kk * 64 + tx * 4 + 2];
                float v3 = Vs[kk * 64 + tx * 4 + 3];
                acc[0][0] += p0 * v0; acc[0][1] += p0 * v1; acc[0][2] += p0 * v2; acc[0][3] += p0 * v3;
                acc[1][0] += p1 * v0; acc[1][1] += p1 * v1; acc[1][2] += p1 * v2; acc[1][3] += p1 * v3;
                acc[2][0] += p2 * v0; acc[2][1] += p2 * v1; acc[2][2] += p2 * v2; acc[2][3] += p2 * v3;
                acc[3][0] += p3 * v0; acc[3][1] += p3 * v1; acc[3][2] += p3 * v2; acc[3][3] += p3 * v3;
            }
        }
        __syncthreads();
    }

    int b = bh >> 5, h = bh & 31;
    int ty = tid >> 4, tx = tid & 15;
#pragma unroll
    for (int i = 0; i < 4; i++) {
        int r = ty * 4 + i;
        float inv = 1.f / lrow[r];
        float* dst = g_o + (size_t)(b * L_ + bq0 + r) * D_ + h * HD_ + tx * 4;
        float4 v = make_float4(acc[i][0] * inv, acc[i][1] * inv,
                               acc[i][2] * inv, acc[i][3] * inv);
        *reinterpret_cast<float4*>(dst) = v;
    }
}

// -------------------------------------------------------------------------
extern "C" void kernel_launch(void* const* d_in, const int* in_sizes, int n_in,
                              void* d_out, int out_size) {
    const float* x     = (const float*)d_in[0];
    const float* cond  = (const float*)d_in[1];
    const float* rope  = (const float*)d_in[2];
    const float* w_ada = (const float*)d_in[3];
    const float* w_qkv = (const float*)d_in[4];
    const float* w_out = (const float*)d_in[5];
    const float* qk_w  = (const float*)d_in[6];
    float* out = (float*)d_out;

    void* p;
    cudaGetSymbolAddress(&p, g_h);   float* ph   = (float*)p;
    cudaGetSymbolAddress(&p, g_qkv); float* pqkv = (float*)p;
    cudaGetSymbolAddress(&p, g_o);   float* po   = (float*)p;

    ada_kernel<<<1024, 256>>>(cond, w_ada);
    rmsada_kernel<<<B_ * L_, 256>>>(x);
    gemm_mma<<<dim3(3 * D_ / 128, B_ * L_ / 128), 256>>>(pqkv, ph, w_qkv,
                                                         B_ * L_, 3 * D_, D_);
    qkrope_kernel<<<(B_ * NH_ * L_) / 8, 256>>>(rope, qk_w);
    attn_kernel<<<dim3(L_ / 64, B_ * NH_), 256>>>();
    gemm_mma<<<dim3(D_ / 128, B_ * L_ / 128), 256>>>(out, po, w_out,
                                                     B_ * L_, D_, D_);
}

// round 4
// speedup vs baseline: 3.2752x; 1.9512x over previous
#include <cuda_runtime.h>
#include <math.h>
#include <stdint.h>

#define B_  2
#define L_  2048
#define D_  2048
#define HD_ 64
#define NH_ 32
#define DC_ 2048
#define EPS 1.1920929e-7f

// ---------------- scratch (device globals; no allocation) ----------------
__device__ float g_ss [B_ * 2 * D_];                 // [b][4096] shift|scale
__device__ float g_h  [(size_t)B_ * L_ * D_];        // modulated hidden
__device__ float g_qkv[(size_t)B_ * L_ * 3 * D_];    // fused qkv rows=(b,l)
__device__ float g_q  [(size_t)B_ * NH_ * L_ * HD_]; // [b][h][l][d]
__device__ float g_k  [(size_t)B_ * NH_ * L_ * HD_];
__device__ float g_v  [(size_t)B_ * NH_ * L_ * HD_];
__device__ float g_o  [(size_t)B_ * L_ * D_];        // rows=(b,l), cols=(h,d)

// ---------------- tf32 helpers ------------------------------------------
__device__ __forceinline__ uint32_t f2tf32(float x) {
    uint32_t u;
    asm("cvt.rna.tf32.f32 %0, %1;" : "=r"(u) : "f"(x));
    return u;
}

__device__ __forceinline__ void mma_tf32(float* c, const uint32_t* a,
                                         const uint32_t* b) {
    asm volatile(
        "mma.sync.aligned.m16n8k8.row.col.f32.tf32.tf32.f32 "
        "{%0,%1,%2,%3}, {%4,%5,%6,%7}, {%8,%9}, {%0,%1,%2,%3};"
        : "+f"(c[0]), "+f"(c[1]), "+f"(c[2]), "+f"(c[3])
        : "r"(a[0]), "r"(a[1]), "r"(a[2]), "r"(a[3]), "r"(b[0]), "r"(b[1]));
}

// ============ tensor-core GEMM NT: C[M,N] = A[M,K] * B[N,K]^T ============
__global__ void __launch_bounds__(256, 2)
gemm_mma(float* __restrict__ C, const float* __restrict__ A,
         const float* __restrict__ B, int M, int N, int K) {
    __shared__ uint32_t As[2][128][20];
    __shared__ uint32_t Bs[2][128][20];

    int tid  = threadIdx.x;
    int m0   = blockIdx.y * 128, n0 = blockIdx.x * 128;
    int wid  = tid >> 5, lane = tid & 31;
    int wm   = (wid & 1) * 64;
    int wn   = (wid >> 1) * 32;
    int qr   = lane >> 2;
    int qc   = lane & 3;

    int lr = tid >> 2;
    int lc = (tid & 3) * 4;

    const float* Ap0 = A + (size_t)(m0 + lr) * K + lc;
    const float* Ap1 = A + (size_t)(m0 + lr + 64) * K + lc;
    const float* Bp0 = B + (size_t)(n0 + lr) * K + lc;
    const float* Bp1 = B + (size_t)(n0 + lr + 64) * K + lc;

    float4 pa0 = *reinterpret_cast<const float4*>(Ap0);
    float4 pa1 = *reinterpret_cast<const float4*>(Ap1);
    float4 pb0 = *reinterpret_cast<const float4*>(Bp0);
    float4 pb1 = *reinterpret_cast<const float4*>(Bp1);

#define STORE_TILE(st)                                                        \
    do {                                                                      \
        uint4 ua0 = make_uint4(f2tf32(pa0.x), f2tf32(pa0.y),                  \
                               f2tf32(pa0.z), f2tf32(pa0.w));                 \
        uint4 ua1 = make_uint4(f2tf32(pa1.x), f2tf32(pa1.y),                  \
                               f2tf32(pa1.z), f2tf32(pa1.w));                 \
        uint4 ub0 = make_uint4(f2tf32(pb0.x), f2tf32(pb0.y),                  \
                               f2tf32(pb0.z), f2tf32(pb0.w));                 \
        uint4 ub1 = make_uint4(f2tf32(pb1.x), f2tf32(pb1.y),                  \
                               f2tf32(pb1.z), f2tf32(pb1.w));                 \
        *reinterpret_cast<uint4*>(&As[st][lr][lc])      = ua0;                \
        *reinterpret_cast<uint4*>(&As[st][lr + 64][lc]) = ua1;                \
        *reinterpret_cast<uint4*>(&Bs[st][lr][lc])      = ub0;                \
        *reinterpret_cast<uint4*>(&Bs[st][lr + 64][lc]) = ub1;                \
    } while (0)

    STORE_TILE(0);
    __syncthreads();

    float acc[4][4][4] = {};
    int s = 0;
    for (int k0 = 16; k0 <= K; k0 += 16) {
        bool last = (k0 == K);
        if (!last) {
            pa0 = *reinterpret_cast<const float4*>(Ap0 + k0);
            pa1 = *reinterpret_cast<const float4*>(Ap1 + k0);
            pb0 = *reinterpret_cast<const float4*>(Bp0 + k0);
            pb1 = *reinterpret_cast<const float4*>(Bp1 + k0);
        }
#pragma unroll
        for (int k8 = 0; k8 < 16; k8 += 8) {
            uint32_t af[4][4], bf[4][2];
#pragma unroll
            for (int mt = 0; mt < 4; mt++) {
                int m = wm + mt * 16 + qr;
                af[mt][0] = As[s][m][k8 + qc];
                af[mt][1] = As[s][m + 8][k8 + qc];
                af[mt][2] = As[s][m][k8 + qc + 4];
                af[mt][3] = As[s][m + 8][k8 + qc + 4];
            }
#pragma unroll
            for (int nt = 0; nt < 4; nt++) {
                int n = wn + nt * 8 + qr;
                bf[nt][0] = Bs[s][n][k8 + qc];
                bf[nt][1] = Bs[s][n][k8 + qc + 4];
            }
#pragma unroll
            for (int mt = 0; mt < 4; mt++)
#pragma unroll
                for (int nt = 0; nt < 4; nt++)
                    mma_tf32(acc[mt][nt], af[mt], bf[nt]);
        }
        if (!last) {
            STORE_TILE(s ^ 1);
            __syncthreads();
            s ^= 1;
        }
    }

#pragma unroll
    for (int mt = 0; mt < 4; mt++) {
        int row = m0 + wm + mt * 16 + qr;
#pragma unroll
        for (int nt = 0; nt < 4; nt++) {
            int col = n0 + wn + nt * 8 + qc * 2;
            *reinterpret_cast<float2*>(C + (size_t)row * N + col) =
                make_float2(acc[mt][nt][0], acc[mt][nt][1]);
            *reinterpret_cast<float2*>(C + (size_t)(row + 8) * N + col) =
                make_float2(acc[mt][nt][2], acc[mt][nt][3]);
        }
    }
#undef STORE_TILE
}

// ---------------- 1) ss = condition @ w_ada^T  (warp per output) ---------
__global__ void ada_kernel(const float* __restrict__ cond,
                           const float* __restrict__ w_ada) {
    int w    = (blockIdx.x * blockDim.x + threadIdx.x) >> 5;
    int lane = threadIdx.x & 31;
    int b = w >> 12;
    int j = w & 4095;
    const float4* c4 = reinterpret_cast<const float4*>(cond + (size_t)b * DC_);
    const float4* w4 = reinterpret_cast<const float4*>(w_ada + (size_t)j * DC_);
    float s = 0.f;
#pragma unroll
    for (int q = 0; q < 16; q++) {
        float4 a  = c4[lane + q * 32];
        float4 bb = w4[lane + q * 32];
        s += a.x * bb.x + a.y * bb.y + a.z * bb.z + a.w * bb.w;
    }
#pragma unroll
    for (int o = 16; o; o >>= 1) s += __shfl_xor_sync(0xffffffffu, s, o);
    if (lane == 0) g_ss[b * 4096 + j] = s;
}

// ---------------- 2) h = rmsnorm(x)*(1+scale)+shift ----------------------
__global__ void rmsada_kernel(const float* __restrict__ x) {
    int row = blockIdx.x;
    int b   = row >> 11;
    int t   = threadIdx.x;
    const float4* xr = reinterpret_cast<const float4*>(x + (size_t)row * D_);
    float4 v0 = xr[t], v1 = xr[t + 256];
    float s = v0.x*v0.x + v0.y*v0.y + v0.z*v0.z + v0.w*v0.w
            + v1.x*v1.x + v1.y*v1.y + v1.z*v1.z + v1.w*v1.w;
    __shared__ float red[256];
    red[t] = s; __syncthreads();
    for (int o = 128; o; o >>= 1) { if (t < o) red[t] += red[t + o]; __syncthreads(); }
    float inv = rsqrtf(red[0] * (1.0f / D_) + EPS);
    const float* shift = g_ss + b * 4096;
    const float* scale = shift + D_;
    float4* hr = reinterpret_cast<float4*>(g_h + (size_t)row * D_);
    {
        int d = t * 4;
        float4 sc = *reinterpret_cast<const float4*>(scale + d);
        float4 sh = *reinterpret_cast<const float4*>(shift + d);
        float4 r;
        r.x = v0.x * inv * (1.f + sc.x) + sh.x;
        r.y = v0.y * inv * (1.f + sc.y) + sh.y;
        r.z = v0.z * inv * (1.f + sc.z) + sh.z;
        r.w = v0.w * inv * (1.f + sc.w) + sh.w;
        hr[t] = r;
    }
    {
        int d = (t + 256) * 4;
        float4 sc = *reinterpret_cast<const float4*>(scale + d);
        float4 sh = *reinterpret_cast<const float4*>(shift + d);
        float4 r;
        r.x = v1.x * inv * (1.f + sc.x) + sh.x;
        r.y = v1.y * inv * (1.f + sc.y) + sh.y;
        r.z = v1.z * inv * (1.f + sc.z) + sh.z;
        r.w = v1.w * inv * (1.f + sc.w) + sh.w;
        hr[t + 256] = r;
    }
}

// ---------------- 4) per-head rmsnorm + qk_w + RoPE, split q/k/v ---------
__global__ void qkrope_kernel(const float* __restrict__ rope,
                              const float* __restrict__ qkw) {
    int wid  = (blockIdx.x * blockDim.x + threadIdx.x) >> 5;
    int lane = threadIdx.x & 31;
    int b   = wid >> 16;
    int rem = wid & 65535;
    int h   = rem >> 11;
    int l   = rem & 2047;
    size_t rowoff = (size_t)(b * L_ + l) * (3 * D_);
    int col = h * HD_ + lane * 2;
    float2 q = *reinterpret_cast<const float2*>(g_qkv + rowoff + col);
    float2 k = *reinterpret_cast<const float2*>(g_qkv + rowoff + D_ + col);
    float2 v = *reinterpret_cast<const float2*>(g_qkv + rowoff + 2 * D_ + col);
    float sq = q.x * q.x + q.y * q.y;
    float sk = k.x * k.x + k.y * k.y;
#pragma unroll
    for (int o = 16; o; o >>= 1) {
        sq += __shfl_xor_sync(0xffffffffu, sq, o);
        sk += __shfl_xor_sync(0xffffffffu, sk, o);
    }
    float qi = rsqrtf(sq * (1.0f / HD_) + EPS);
    float ki = rsqrtf(sk * (1.0f / HD_) + EPS);
    float2 w2 = *reinterpret_cast<const float2*>(qkw + lane * 2);
    float q0 = q.x * qi * w2.x, q1 = q.y * qi * w2.y;
    float k0 = k.x * ki * w2.x, k1 = k.y * ki * w2.y;
    float2 r0 = *reinterpret_cast<const float2*>(rope + (size_t)l * HD_ + lane * 2);
    float2 r1 = *reinterpret_cast<const float2*>(rope + (size_t)(L_ + l) * HD_ + lane * 2);
    float2 qo, ko;
    qo.x = q0 * r0.x - q1 * r1.x;
    qo.y = q1 * r0.y + q0 * r1.y;
    ko.x = k0 * r0.x - k1 * r1.x;
    ko.y = k1 * r0.y + k0 * r1.y;
    size_t orow = (size_t)wid * HD_ + lane * 2;
    *reinterpret_cast<float2*>(g_q + orow) = qo;
    *reinterpret_cast<float2*>(g_k + orow) = ko;
    *reinterpret_cast<float2*>(g_v + orow) = v;
}

// ============ 5) tensor-core flash attention =============================
// BQ=64 (4 warps x 16 rows), BC=32 keys/chunk, m16n8k8 tf32 MMA.
__global__ void __launch_bounds__(128, 2) attn_mma() {
    __shared__ uint32_t KQ[64][68];   // Q staging (raw f32 bits) / K chunk (tf32, rows 0..31)
    __shared__ uint32_t Vs[32][72];   // V chunk (tf32)
    __shared__ uint32_t Ps[64][36];   // P (tf32)

    int tid  = threadIdx.x;
    int wid  = tid >> 5, lane = tid & 31;
    int qr   = lane >> 2, qc = lane & 3;
    int bh   = blockIdx.y;
    int bq0  = blockIdx.x * 64;
    int qrow = wid * 16 + qr;

    const float* Qg = g_q + (size_t)bh * L_ * HD_;
    const float* Kg = g_k + (size_t)bh * L_ * HD_;
    const float* Vg = g_v + (size_t)bh * L_ * HD_;

    // prefetch chunk 0 of K/V into registers
    int pr = tid >> 4;                 // 0..7  (+8,16,24 across t)
    int pc = (tid & 15) * 4;
    float4 kp[4], vp[4];
#pragma unroll
    for (int t = 0; t < 4; t++) {
        int r = pr + t * 8;
        kp[t] = *reinterpret_cast<const float4*>(Kg + (size_t)r * HD_ + pc);
        vp[t] = *reinterpret_cast<const float4*>(Vg + (size_t)r * HD_ + pc);
    }

    // stage Q (pre-scaled by 1/sqrt(64)) into KQ as raw f32 bits
#pragma unroll
    for (int t = 0; t < 8; t++) {
        int idx = tid + t * 128;
        int r = idx >> 4, c = (idx & 15) * 4;
        float4 v = *reinterpret_cast<const float4*>(Qg + (size_t)(bq0 + r) * HD_ + c);
        uint4 u = make_uint4(__float_as_uint(v.x * 0.125f),
                             __float_as_uint(v.y * 0.125f),
                             __float_as_uint(v.z * 0.125f),
                             __float_as_uint(v.w * 0.125f));
        *reinterpret_cast<uint4*>(&KQ[r][c]) = u;
    }
    __syncthreads();

    // Q fragments (tf32), held in registers for whole kernel
    uint32_t aq[8][4];
#pragma unroll
    for (int kk = 0; kk < 8; kk++) {
        aq[kk][0] = f2tf32(__uint_as_float(KQ[qrow][8 * kk + qc]));
        aq[kk][1] = f2tf32(__uint_as_float(KQ[qrow + 8][8 * kk + qc]));
        aq[kk][2] = f2tf32(__uint_as_float(KQ[qrow][8 * kk + qc + 4]));
        aq[kk][3] = f2tf32(__uint_as_float(KQ[qrow + 8][8 * kk + qc + 4]));
    }

    float o[8][4] = {};
    float m_lo = -INFINITY, m_hi = -INFINITY, l_lo = 0.f, l_hi = 0.f;

    for (int c64 = 0; c64 < 64; c64++) {
        __syncthreads();               // prior reads of KQ/Vs done
        // store prefetched K/V chunk (convert to tf32)
#pragma unroll
        for (int t = 0; t < 4; t++) {
            int r = pr + t * 8;
            uint4 uk = make_uint4(f2tf32(kp[t].x), f2tf32(kp[t].y),
                                  f2tf32(kp[t].z), f2tf32(kp[t].w));
            uint4 uv = make_uint4(f2tf32(vp[t].x), f2tf32(vp[t].y),
                                  f2tf32(vp[t].z), f2tf32(vp[t].w));
            *reinterpret_cast<uint4*>(&KQ[r][pc]) = uk;
            *reinterpret_cast<uint4*>(&Vs[r][pc]) = uv;
        }
        __syncthreads();
        // issue loads for next chunk (overlap with compute)
        if (c64 < 63) {
            size_t koff = (size_t)(c64 + 1) * 32;
#pragma unroll
            for (int t = 0; t < 4; t++) {
                int r = pr + t * 8;
                kp[t] = *reinterpret_cast<const float4*>(Kg + (koff + r) * HD_ + pc);
                vp[t] = *reinterpret_cast<const float4*>(Vg + (koff + r) * HD_ + pc);
            }
        }

        // ---- S = Q K^T (m16 x n32 per warp) ----
        float s[4][4] = {};
#pragma unroll
        for (int kk = 0; kk < 8; kk++) {
#pragma unroll
            for (int j = 0; j < 4; j++) {
                uint32_t bk[2];
                bk[0] = KQ[j * 8 + qr][8 * kk + qc];
                bk[1] = KQ[j * 8 + qr][8 * kk + qc + 4];
                mma_tf32(s[j], aq[kk], bk);
            }
        }

        // ---- online softmax in fragment layout ----
        float mx_lo = -INFINITY, mx_hi = -INFINITY;
#pragma unroll
        for (int j = 0; j < 4; j++) {
            mx_lo = fmaxf(mx_lo, fmaxf(s[j][0], s[j][1]));
            mx_hi = fmaxf(mx_hi, fmaxf(s[j][2], s[j][3]));
        }
        mx_lo = fmaxf(mx_lo, __shfl_xor_sync(0xffffffffu, mx_lo, 1));
        mx_lo = fmaxf(mx_lo, __shfl_xor_sync(0xffffffffu, mx_lo, 2));
        mx_hi = fmaxf(mx_hi, __shfl_xor_sync(0xffffffffu, mx_hi, 1));
        mx_hi = fmaxf(mx_hi, __shfl_xor_sync(0xffffffffu, mx_hi, 2));

        float mn_lo = fmaxf(m_lo, mx_lo);
        float mn_hi = fmaxf(m_hi, mx_hi);
        float cf_lo = __expf(m_lo - mn_lo);
        float cf_hi = __expf(m_hi - mn_hi);
        m_lo = mn_lo; m_hi = mn_hi;

        float ls_lo = 0.f, ls_hi = 0.f;
        uint32_t p[4][4];
#pragma unroll
        for (int j = 0; j < 4; j++) {
            uint32_t u0 = f2tf32(__expf(s[j][0] - mn_lo));
            uint32_t u1 = f2tf32(__expf(s[j][1] - mn_lo));
            uint32_t u2 = f2tf32(__expf(s[j][2] - mn_hi));
            uint32_t u3 = f2tf32(__expf(s[j][3] - mn_hi));
            p[j][0] = u0; p[j][1] = u1; p[j][2] = u2; p[j][3] = u3;
            ls_lo += __uint_as_float(u0) + __uint_as_float(u1);
            ls_hi += __uint_as_float(u2) + __uint_as_float(u3);
        }
        ls_lo += __shfl_xor_sync(0xffffffffu, ls_lo, 1);
        ls_lo += __shfl_xor_sync(0xffffffffu, ls_lo, 2);
        ls_hi += __shfl_xor_sync(0xffffffffu, ls_hi, 1);
        ls_hi += __shfl_xor_sync(0xffffffffu, ls_hi, 2);
        l_lo = l_lo * cf_lo + ls_lo;
        l_hi = l_hi * cf_hi + ls_hi;

#pragma unroll
        for (int n = 0; n < 8; n++) {
            o[n][0] *= cf_lo; o[n][1] *= cf_lo;
            o[n][2] *= cf_hi; o[n][3] *= cf_hi;
        }

        // ---- P to smem (same warp reads back its own rows) ----
#pragma unroll
        for (int j = 0; j < 4; j++) {
            *reinterpret_cast<uint2*>(&Ps[qrow][8 * j + 2 * qc]) =
                make_uint2(p[j][0], p[j][1]);
            *reinterpret_cast<uint2*>(&Ps[qrow + 8][8 * j + 2 * qc]) =
                make_uint2(p[j][2], p[j][3]);
        }
        __syncwarp();

        // ---- O += P V ----
#pragma unroll
        for (int kk2 = 0; kk2 < 4; kk2++) {
            uint32_t ap[4];
            ap[0] = Ps[qrow][8 * kk2 + qc];
            ap[1] = Ps[qrow + 8][8 * kk2 + qc];
            ap[2] = Ps[qrow][8 * kk2 + qc + 4];
            ap[3] = Ps[qrow + 8][8 * kk2 + qc + 4];
#pragma unroll
            for (int n = 0; n < 8; n++) {
                uint32_t bv[2];
                bv[0] = Vs[8 * kk2 + qc][8 * n + qr];
                bv[1] = Vs[8 * kk2 + qc + 4][8 * n + qr];
                mma_tf32(o[n], ap, bv);
            }
        }
        __syncwarp();
    }

    // epilogue: normalize and write to g_o rows=(b,l), cols=(h,d)
    int b = bh >> 5, h = bh & 31;
    float inv_lo = 1.f / l_lo, inv_hi = 1.f / l_hi;
    float* base_lo = g_o + (size_t)(b * L_ + bq0 + qrow) * D_ + h * HD_;
    float* base_hi = g_o + (size_t)(b * L_ + bq0 + qrow + 8) * D_ + h * HD_;
#pragma unroll
    for (int n = 0; n < 8; n++) {
        *reinterpret_cast<float2*>(base_lo + 8 * n + 2 * qc) =
            make_float2(o[n][0] * inv_lo, o[n][1] * inv_lo);
        *reinterpret_cast<float2*>(base_hi + 8 * n + 2 * qc) =
            make_float2(o[n][2] * inv_hi, o[n][3] * inv_hi);
    }
}

// -------------------------------------------------------------------------
extern "C" void kernel_launch(void* const* d_in, const int* in_sizes, int n_in,
                              void* d_out, int out_size) {
    const float* x     = (const float*)d_in[0];
    const float* cond  = (const float*)d_in[1];
    const float* rope  = (const float*)d_in[2];
    const float* w_ada = (const float*)d_in[3];
    const float* w_qkv = (const float*)d_in[4];
    const float* w_out = (const float*)d_in[5];
    const float* qk_w  = (const float*)d_in[6];
    float* out = (float*)d_out;

    void* p;
    cudaGetSymbolAddress(&p, g_h);   float* ph   = (float*)p;
    cudaGetSymbolAddress(&p, g_qkv); float* pqkv = (float*)p;
    cudaGetSymbolAddress(&p, g_o);   float* po   = (float*)p;

    ada_kernel<<<1024, 256>>>(cond, w_ada);
    rmsada_kernel<<<B_ * L_, 256>>>(x);
    gemm_mma<<<dim3(3 * D_ / 128, B_ * L_ / 128), 256>>>(pqkv, ph, w_qkv,
                                                         B_ * L_, 3 * D_, D_);
    qkrope_kernel<<<(B_ * NH_ * L_) / 8, 256>>>(rope, qk_w);
    attn_mma<<<dim3(L_ / 64, B_ * NH_), 128>>>();
    gemm_mma<<<dim3(D_ / 128, B_ * L_ / 128), 256>>>(out, po, w_out,
                                                     B_ * L_, D_, D_);
}